// round 4
// baseline (speedup 1.0000x reference)
#include <cuda_runtime.h>
#include <math.h>

// Problem constants
#define HW    4096
#define NIMG  64
#define DM    64
#define DS    16
#define NB    4

// Scratch (device globals; no allocation allowed)
__device__ float g_h[64];
__device__ float g_mu[16];
__device__ float g_rstd[16];
__device__ float g_un[NB*DM*HW];      // 4MB
__device__ float g_delta[NB*DM*HW];   // 4MB
__device__ float g_Bval[NB*DS*HW];    // 1MB
__device__ float g_Cval[NB*DS*HW];    // 1MB

typedef unsigned long long ull;

__device__ __forceinline__ ull pk2(float x) {
    ull r; asm("mov.b64 %0,{%1,%1};" : "=l"(r) : "f"(x)); return r;
}
__device__ __forceinline__ void fma2(ull &a, ull b, ull c) {
    asm("fma.rn.f32x2 %0,%1,%2,%0;" : "+l"(a) : "l"(b), "l"(c));
}
__device__ __forceinline__ float2 up2(ull a) {
    float2 v; asm("mov.b64 {%0,%1},%2;" : "=f"(v.x), "=f"(v.y) : "l"(a)); return v;
}

// ---------------------------------------------------------------------------
// K0: spectral-derivative circular kernel h[n] (exact definition, fp64 sum)
// grad[j] = sum_p x[p] * h[(j-p) mod 64]
// ---------------------------------------------------------------------------
__global__ void k_init_h() {
    int n = threadIdx.x;  // 0..63
    double acc = 0.0;
    for (int m = 1; m < 32; m++) {
        double km = 2.0 * 3.141592653589793238 * (double)m / 64.0;
        acc += km * sin(km * (double)n);
    }
    g_h[n] = (float)(-acc * 2.0 / 64.0);
}

// ---------------------------------------------------------------------------
// K1a: GroupNorm statistics. One block per (b,g); region is contiguous 65536.
// ---------------------------------------------------------------------------
__global__ void k_stats(const float* __restrict__ u) {
    int bg = blockIdx.x;
    const float* base = u + bg * 65536;
    float s = 0.f, s2 = 0.f;
    for (int i = threadIdx.x; i < 65536; i += 256) {
        float v = base[i];
        s += v; s2 = fmaf(v, v, s2);
    }
    for (int o = 16; o; o >>= 1) {
        s  += __shfl_down_sync(0xFFFFFFFFu, s,  o);
        s2 += __shfl_down_sync(0xFFFFFFFFu, s2, o);
    }
    __shared__ float ss[8], ss2[8];
    int w = threadIdx.x >> 5, l = threadIdx.x & 31;
    if (l == 0) { ss[w] = s; ss2[w] = s2; }
    __syncthreads();
    if (threadIdx.x == 0) {
        float S = 0.f, S2 = 0.f;
        #pragma unroll
        for (int i = 0; i < 8; i++) { S += ss[i]; S2 += ss2[i]; }
        float mu  = S  * (1.f / 65536.f);
        float var = S2 * (1.f / 65536.f) - mu * mu;
        g_mu[bg]   = mu;
        g_rstd[bg] = rsqrtf(var + 1e-5f);
    }
}

// ---------------------------------------------------------------------------
// K1b: normalize -> g_un
// ---------------------------------------------------------------------------
__global__ void k_norm(const float* __restrict__ u,
                       const float* __restrict__ gamma,
                       const float* __restrict__ beta) {
    int idx = blockIdx.x * 256 + threadIdx.x;       // < 1048576
    int c  = (idx >> 12) & 63;
    int bg = (idx >> 18) * 4 + (c >> 4);
    g_un[idx] = (u[idx] - g_mu[bg]) * g_rstd[bg] * gamma[c] + beta[c];
}

// ---------------------------------------------------------------------------
// K2: fused circular 3x3 convs: 96 out channels (64 delta | 16 B | 16 C).
// Block = (batch, 8x8 spatial tile), 256 threads = 16 oc-groups x 16 px-groups.
// Thread computes 6 oc x (2x2) px. ic chunked by 8 through shared memory.
// ---------------------------------------------------------------------------
__global__ void k_conv(const float* __restrict__ wd, const float* __restrict__ bd,
                       const float* __restrict__ wB, const float* __restrict__ wC,
                       const float* __restrict__ dtp) {
    __shared__ float ws[96 * 72];        // [oc][icl(8)][tap(9)]
    __shared__ float xs[8 * 120];        // [icl][10 rows][12 pad cols]

    int bx = blockIdx.x;
    int b  = bx >> 6;
    int t  = bx & 63;
    int y0 = (t >> 3) * 8;
    int x0 = (t & 7) * 8;

    int tid = threadIdx.x;
    int ocg = tid >> 4;            // 0..15
    int pxg = tid & 15;            // 0..15
    int oc0 = ocg * 6;
    int py0 = (pxg >> 2) * 2;
    int px0 = (pxg & 3) * 2;

    float acc[6][4];
    #pragma unroll
    for (int j = 0; j < 6; j++)
        #pragma unroll
        for (int q = 0; q < 4; q++) acc[j][q] = 0.f;

    for (int ic0 = 0; ic0 < 64; ic0 += 8) {
        __syncthreads();
        // weights for this ic chunk: 96*8*9 = 6912 floats
        for (int l = tid; l < 6912; l += 256) {
            int oc = l / 72, rem = l - oc * 72;
            float v;
            if (oc < 64)       v = wd[oc * 576 + ic0 * 9 + rem];
            else if (oc < 80)  v = wB[(oc - 64) * 576 + ic0 * 9 + rem];
            else               v = wC[(oc - 80) * 576 + ic0 * 9 + rem];
            ws[l] = v;
        }
        // input halo tile: 8 ch x 10 x 10 with circular wrap
        for (int l = tid; l < 800; l += 256) {
            int icl = l / 100, r = l - icl * 100;
            int yy = r / 10, xx = r - yy * 10;
            int gy = (y0 + yy - 1) & 63;
            int gx = (x0 + xx - 1) & 63;
            xs[icl * 120 + yy * 12 + xx] =
                g_un[((b * 64 + ic0 + icl) * 64 + gy) * 64 + gx];
        }
        __syncthreads();

        for (int icl = 0; icl < 8; icl++) {
            int wb0 = oc0 * 72 + icl * 9;
            int xb0 = icl * 120 + py0 * 12 + px0;
            #pragma unroll
            for (int dy = 0; dy < 3; dy++) {
                #pragma unroll
                for (int dx = 0; dx < 3; dx++) {
                    int tap = dy * 3 + dx;
                    float w0 = ws[wb0 + tap];
                    float w1 = ws[wb0 + 72  + tap];
                    float w2 = ws[wb0 + 144 + tap];
                    float w3 = ws[wb0 + 216 + tap];
                    float w4 = ws[wb0 + 288 + tap];
                    float w5 = ws[wb0 + 360 + tap];
                    int xb = xb0 + dy * 12 + dx;
                    float xa = xs[xb], xbv = xs[xb + 1];
                    float xc = xs[xb + 12], xd = xs[xb + 13];
                    acc[0][0] = fmaf(w0, xa, acc[0][0]); acc[0][1] = fmaf(w0, xbv, acc[0][1]);
                    acc[0][2] = fmaf(w0, xc, acc[0][2]); acc[0][3] = fmaf(w0, xd, acc[0][3]);
                    acc[1][0] = fmaf(w1, xa, acc[1][0]); acc[1][1] = fmaf(w1, xbv, acc[1][1]);
                    acc[1][2] = fmaf(w1, xc, acc[1][2]); acc[1][3] = fmaf(w1, xd, acc[1][3]);
                    acc[2][0] = fmaf(w2, xa, acc[2][0]); acc[2][1] = fmaf(w2, xbv, acc[2][1]);
                    acc[2][2] = fmaf(w2, xc, acc[2][2]); acc[2][3] = fmaf(w2, xd, acc[2][3]);
                    acc[3][0] = fmaf(w3, xa, acc[3][0]); acc[3][1] = fmaf(w3, xbv, acc[3][1]);
                    acc[3][2] = fmaf(w3, xc, acc[3][2]); acc[3][3] = fmaf(w3, xd, acc[3][3]);
                    acc[4][0] = fmaf(w4, xa, acc[4][0]); acc[4][1] = fmaf(w4, xbv, acc[4][1]);
                    acc[4][2] = fmaf(w4, xc, acc[4][2]); acc[4][3] = fmaf(w4, xd, acc[4][3]);
                    acc[5][0] = fmaf(w5, xa, acc[5][0]); acc[5][1] = fmaf(w5, xbv, acc[5][1]);
                    acc[5][2] = fmaf(w5, xc, acc[5][2]); acc[5][3] = fmaf(w5, xd, acc[5][3]);
                }
            }
        }
    }

    float dtv = __ldg(dtp);
    int yb = y0 + py0, xb = x0 + px0;
    int pix[4] = { yb * 64 + xb, yb * 64 + xb + 1,
                   (yb + 1) * 64 + xb, (yb + 1) * 64 + xb + 1 };

    #pragma unroll
    for (int jj = 0; jj < 6; jj++) {
        int oc = oc0 + jj;
        if (oc < 64) {
            float bias = bd[oc] + dtv;
            float* dst = g_delta + (b * 64 + oc) * HW;
            #pragma unroll
            for (int q = 0; q < 4; q++) {
                float v = acc[jj][q] + bias;
                float sp = (v > 0.f) ? (v + log1pf(expf(-v))) : log1pf(expf(v));
                sp = fminf(fmaxf(sp, 1e-4f), 5.0f);
                dst[pix[q]] = sp;
            }
        } else if (oc < 80) {
            float* dst = g_Bval + (b * 16 + (oc - 64)) * HW;
            #pragma unroll
            for (int q = 0; q < 4; q++) dst[pix[q]] = acc[jj][q];
        } else {
            float* dst = g_Cval + (b * 16 + (oc - 80)) * HW;
            #pragma unroll
            for (int q = 0; q < 4; q++) dst[pix[q]] = acc[jj][q];
        }
    }
}

// ---------------------------------------------------------------------------
// K3: per-(b,d,n) plane: spectral gradients (circulant matmuls, fp32x2 FMA)
// fused with state update. Writes s_new (m0,mx,my) into d_out.
// Block = 128 threads; thread tile = 4 rows x 8 cols.
// ---------------------------------------------------------------------------
__global__ void __launch_bounds__(128) k_update(
        const float* __restrict__ u, const float* __restrict__ sprev,
        const float* __restrict__ logA, float* __restrict__ out) {
    __shared__ float  Xs[64 * 66];
    __shared__ float  hh2[128];
    __shared__ float2 hp[128];

    int tid = threadIdx.x;
    int bp  = blockIdx.x;            // b*1024 + d*16 + n
    int b = bp >> 10, d = (bp >> 4) & 63, n = bp & 15;

    const float* m0p = sprev + (((b * 3 + 0) * 64 + d) * 16 + n) * HW;
    for (int l = tid; l < 4096; l += 128)
        Xs[(l >> 6) * 66 + (l & 63)] = m0p[l];
    hh2[tid] = g_h[tid & 63];
    if (tid < 127) hp[tid] = make_float2(g_h[tid & 63], g_h[(tid + 1) & 63]);
    __syncthreads();

    int rg = tid >> 3, cg = tid & 7;
    int r0 = rg * 4, c0 = cg * 8;

    ull gxa[4][4], gya[4][4];
    #pragma unroll
    for (int i = 0; i < 4; i++)
        #pragma unroll
        for (int p = 0; p < 4; p++) { gxa[i][p] = 0ull; gya[i][p] = 0ull; }

    #pragma unroll 2
    for (int k = 0; k < 64; k++) {
        ull xr[4], hy[4];
        #pragma unroll
        for (int i = 0; i < 4; i++) {
            xr[i] = pk2(Xs[(r0 + i) * 66 + k]);
            hy[i] = pk2(hh2[r0 + i - k + 64]);
        }
        int qb = c0 - k + 64;
        ull hx[4], xc[4];
        #pragma unroll
        for (int p = 0; p < 4; p++) {
            hx[p] = *(const ull*)&hp[qb + 2 * p];
            xc[p] = *(const ull*)&Xs[k * 66 + c0 + 2 * p];
        }
        #pragma unroll
        for (int i = 0; i < 4; i++)
            #pragma unroll
            for (int p = 0; p < 4; p++) {
                fma2(gxa[i][p], xr[i], hx[p]);   // grad_x: sum_k X[r][k] h[c-k]
                fma2(gya[i][p], hy[i], xc[p]);   // grad_y: sum_k h[r-k] X[k][c]
            }
    }

    float Adn = -expf(__ldg(&logA[d * 16 + n]));
    int pb_bd = (b * 64 + d) * HW;
    int pb_bn = (b * 16 + n) * HW;
    int sp0 = (((b * 3 + 0) * 64 + d) * 16 + n) * HW;
    int sp1 = (((b * 3 + 1) * 64 + d) * 16 + n) * HW;
    int sp2 = (((b * 3 + 2) * 64 + d) * 16 + n) * HW;
    const int so = NB * DM * HW;   // y_new size = 1048576

    #pragma unroll
    for (int i = 0; i < 4; i++) {
        int off = (r0 + i) * 64 + c0;
        float4 dv0 = *(const float4*)(g_delta + pb_bd + off);
        float4 dv1 = *(const float4*)(g_delta + pb_bd + off + 4);
        float4 uv0 = *(const float4*)(u + pb_bd + off);
        float4 uv1 = *(const float4*)(u + pb_bd + off + 4);
        float4 bv0 = *(const float4*)(g_Bval + pb_bn + off);
        float4 bv1 = *(const float4*)(g_Bval + pb_bn + off + 4);
        float4 mx0 = *(const float4*)(sprev + sp1 + off);
        float4 mx1 = *(const float4*)(sprev + sp1 + off + 4);
        float4 my0 = *(const float4*)(sprev + sp2 + off);
        float4 my1 = *(const float4*)(sprev + sp2 + off + 4);

        float dd[8] = { dv0.x, dv0.y, dv0.z, dv0.w, dv1.x, dv1.y, dv1.z, dv1.w };
        float uu[8] = { uv0.x, uv0.y, uv0.z, uv0.w, uv1.x, uv1.y, uv1.z, uv1.w };
        float bb[8] = { bv0.x, bv0.y, bv0.z, bv0.w, bv1.x, bv1.y, bv1.z, bv1.w };
        float mx[8] = { mx0.x, mx0.y, mx0.z, mx0.w, mx1.x, mx1.y, mx1.z, mx1.w };
        float my[8] = { my0.x, my0.y, my0.z, my0.w, my1.x, my1.y, my1.z, my1.w };

        float gx[8], gy[8];
        #pragma unroll
        for (int p = 0; p < 4; p++) {
            float2 a = up2(gxa[i][p]); gx[2 * p] = a.x; gx[2 * p + 1] = a.y;
            float2 c = up2(gya[i][p]); gy[2 * p] = c.x; gy[2 * p + 1] = c.y;
        }

        float m0n[8], mxn[8], myn[8];
        #pragma unroll
        for (int j = 0; j < 8; j++) {
            float m0v = Xs[(r0 + i) * 66 + c0 + j];
            float Ab  = expf(dd[j] * Adn);
            m0n[j] = fmaf(Ab, m0v, dd[j] * bb[j] * uu[j]);
            mxn[j] = Ab * (mx[j] - gx[j]);
            myn[j] = Ab * (my[j] - gy[j]);
        }
        *(float4*)(out + so + sp0 + off)     = make_float4(m0n[0], m0n[1], m0n[2], m0n[3]);
        *(float4*)(out + so + sp0 + off + 4) = make_float4(m0n[4], m0n[5], m0n[6], m0n[7]);
        *(float4*)(out + so + sp1 + off)     = make_float4(mxn[0], mxn[1], mxn[2], mxn[3]);
        *(float4*)(out + so + sp1 + off + 4) = make_float4(mxn[4], mxn[5], mxn[6], mxn[7]);
        *(float4*)(out + so + sp2 + off)     = make_float4(myn[0], myn[1], myn[2], myn[3]);
        *(float4*)(out + so + sp2 + off + 4) = make_float4(myn[4], myn[5], myn[6], myn[7]);
    }
}

// ---------------------------------------------------------------------------
// K4: y[b,d,p] = sum_n m0_new[b,d,n,p] * C_val[b,n,p] + u*D[d]
// ---------------------------------------------------------------------------
__global__ void k_y(const float* __restrict__ u, const float* __restrict__ Dp,
                    float* __restrict__ out) {
    int idx = blockIdx.x * 256 + threadIdx.x;   // < 1048576
    int b = idx >> 18;
    int d = (idx >> 12) & 63;
    int p = idx & 4095;
    const int so = NB * DM * HW;
    const float* m0n = out + so + ((b * 3 * 64 + d) * 16) * HW + p;
    const float* Cv  = g_Cval + (b * 16) * HW + p;
    float acc = 0.f;
    #pragma unroll
    for (int nn = 0; nn < 16; nn++)
        acc = fmaf(m0n[nn * HW], Cv[nn * HW], acc);
    out[idx] = fmaf(u[idx], Dp[d], acc);
}

// ---------------------------------------------------------------------------
extern "C" void kernel_launch(void* const* d_in, const int* in_sizes, int n_in,
                              void* d_out, int out_size) {
    const float* u     = (const float*)d_in[0];
    const float* sprev = (const float*)d_in[1];
    const float* gamma = (const float*)d_in[2];
    const float* beta  = (const float*)d_in[3];
    const float* wd    = (const float*)d_in[4];
    const float* bd    = (const float*)d_in[5];
    const float* wB    = (const float*)d_in[6];
    const float* wC    = (const float*)d_in[7];
    const float* logA  = (const float*)d_in[8];
    const float* Dp    = (const float*)d_in[9];
    const float* dt    = (const float*)d_in[10];
    float* out = (float*)d_out;

    k_init_h<<<1, 64>>>();
    k_stats<<<16, 256>>>(u);
    k_norm<<<4096, 256>>>(u, gamma, beta);
    k_conv<<<256, 256>>>(wd, bd, wB, wC, dt);
    k_update<<<4096, 128>>>(u, sprev, logA, out);
    k_y<<<4096, 256>>>(u, Dp, out);
}

// round 5
// speedup vs baseline: 1.5536x; 1.5536x over previous
#include <cuda_runtime.h>
#include <math.h>

#define HW    4096
#define DM    64
#define DS    16
#define NB    4

// Scratch (device globals; no allocation allowed)
__device__ float g_h[64];
__device__ float g_mu[16];
__device__ float g_rstd[16];
__device__ float g_delta[NB*DM*HW];   // 4MB
__device__ float g_Bval[NB*DS*HW];    // 1MB
__device__ float g_Cval[NB*DS*HW];    // 1MB

typedef unsigned long long ull;

__device__ __forceinline__ ull pk2(float x) {
    ull r; asm("mov.b64 %0,{%1,%1};" : "=l"(r) : "f"(x)); return r;
}
__device__ __forceinline__ ull pk(float lo, float hi) {
    ull r; asm("mov.b64 %0,{%1,%2};" : "=l"(r) : "f"(lo), "f"(hi)); return r;
}
__device__ __forceinline__ void fma2(ull &a, ull b, ull c) {
    asm("fma.rn.f32x2 %0,%1,%2,%0;" : "+l"(a) : "l"(b), "l"(c));
}
__device__ __forceinline__ float2 up2(ull a) {
    float2 v; asm("mov.b64 {%0,%1},%2;" : "=f"(v.x), "=f"(v.y) : "l"(a)); return v;
}

// ---------------------------------------------------------------------------
// K0: spectral-derivative circular kernel h[n] (exact, fp64 accumulation)
// ---------------------------------------------------------------------------
__global__ void k_init_h() {
    int n = threadIdx.x;  // 0..63
    double acc = 0.0;
    for (int m = 1; m < 32; m++) {
        double km = 2.0 * 3.141592653589793238 * (double)m / 64.0;
        acc += km * sin(km * (double)n);
    }
    g_h[n] = (float)(-acc * 2.0 / 64.0);
}

// ---------------------------------------------------------------------------
// K1: GroupNorm statistics. One block per (b,g); 1024 threads, float4.
// ---------------------------------------------------------------------------
__global__ void __launch_bounds__(1024) k_stats(const float* __restrict__ u) {
    int bg = blockIdx.x;
    const float4* base = (const float4*)(u + bg * 65536);
    float s = 0.f, s2 = 0.f;
    for (int i = threadIdx.x; i < 16384; i += 1024) {
        float4 v = base[i];
        s += v.x + v.y + v.z + v.w;
        s2 = fmaf(v.x, v.x, s2); s2 = fmaf(v.y, v.y, s2);
        s2 = fmaf(v.z, v.z, s2); s2 = fmaf(v.w, v.w, s2);
    }
    for (int o = 16; o; o >>= 1) {
        s  += __shfl_down_sync(0xFFFFFFFFu, s,  o);
        s2 += __shfl_down_sync(0xFFFFFFFFu, s2, o);
    }
    __shared__ float ss[32], ss2[32];
    int w = threadIdx.x >> 5, l = threadIdx.x & 31;
    if (l == 0) { ss[w] = s; ss2[w] = s2; }
    __syncthreads();
    if (threadIdx.x == 0) {
        float S = 0.f, S2 = 0.f;
        #pragma unroll
        for (int i = 0; i < 32; i++) { S += ss[i]; S2 += ss2[i]; }
        float mu  = S  * (1.f / 65536.f);
        float var = S2 * (1.f / 65536.f) - mu * mu;
        g_mu[bg]   = mu;
        g_rstd[bg] = rsqrtf(var + 1e-5f);
    }
}

// ---------------------------------------------------------------------------
// K2: fused GroupNorm + circular 3x3 convs: 96 oc (64 delta | 16 B | 16 C).
// Grid 512 = (4 batch) x (8 row-tiles x 16 col-tiles of 8x4).
// 128 threads = 16 ocg x 8 pxg; thread = 6 oc x (2x2) px.
// ---------------------------------------------------------------------------
__global__ void __launch_bounds__(128) k_conv(
        const float* __restrict__ u,
        const float* __restrict__ gamma, const float* __restrict__ beta,
        const float* __restrict__ wd, const float* __restrict__ bd,
        const float* __restrict__ wB, const float* __restrict__ wC,
        const float* __restrict__ dtp) {
    __shared__ float ws[96 * 76];        // [oc][icl(8) x tap(9)] padded to 76
    __shared__ float xs[8 * 60];         // [icl][10 rows][6 cols]
    __shared__ float cs_scale[64], cs_shift[64];

    int bx = blockIdx.x;
    int b  = bx >> 7;
    int t  = bx & 127;
    int y0 = (t >> 4) * 8;
    int x0 = (t & 15) * 4;

    int tid = threadIdx.x;
    int ocg = tid >> 3;            // 0..15
    int pxg = tid & 7;             // 0..7
    int oc0 = ocg * 6;
    int py0 = (pxg >> 1) * 2;      // 0,2,4,6
    int px0 = (pxg & 1) * 2;       // 0,2

    if (tid < 64) {
        int bg = b * 4 + (tid >> 4);
        float rs = g_rstd[bg] * gamma[tid];
        cs_scale[tid] = rs;
        cs_shift[tid] = beta[tid] - g_mu[bg] * rs;
    }

    float acc[6][4];
    #pragma unroll
    for (int j = 0; j < 6; j++)
        #pragma unroll
        for (int q = 0; q < 4; q++) acc[j][q] = 0.f;

    for (int ic0 = 0; ic0 < 64; ic0 += 8) {
        __syncthreads();
        int chunk = ic0 >> 3;
        // weights: 1728 float4 into padded layout
        for (int l4 = tid; l4 < 1728; l4 += 128) {
            int oc  = l4 / 18;
            int rem = l4 - oc * 18;
            float4 v;
            if (oc < 64)       v = ((const float4*)wd)[oc * 144 + chunk * 18 + rem];
            else if (oc < 80)  v = ((const float4*)wB)[(oc - 64) * 144 + chunk * 18 + rem];
            else               v = ((const float4*)wC)[(oc - 80) * 144 + chunk * 18 + rem];
            *((float4*)(ws + oc * 76) + rem) = v;
        }
        // normalized halo tile: 8 ch x 10 x 6, circular wrap
        for (int l = tid; l < 480; l += 128) {
            int icl = l / 60; int r = l - icl * 60;
            int yy = r / 6, xx = r - yy * 6;
            int gy = (y0 + yy - 1) & 63;
            int gx = (x0 + xx - 1) & 63;
            int c  = ic0 + icl;
            float v = u[((b * 64 + c) * 64 + gy) * 64 + gx];
            xs[icl * 60 + yy * 6 + xx] = fmaf(v, cs_scale[c], cs_shift[c]);
        }
        __syncthreads();

        #pragma unroll
        for (int icl = 0; icl < 8; icl++) {
            const float* wp = ws + oc0 * 76 + icl * 9;
            const float* xp = xs + icl * 60 + py0 * 6 + px0;
            float xv[4][4];
            #pragma unroll
            for (int rr = 0; rr < 4; rr++)
                #pragma unroll
                for (int cc = 0; cc < 4; cc++) xv[rr][cc] = xp[rr * 6 + cc];
            #pragma unroll
            for (int dy = 0; dy < 3; dy++) {
                #pragma unroll
                for (int dx = 0; dx < 3; dx++) {
                    int tap = dy * 3 + dx;
                    float xa = xv[dy][dx],     xb2 = xv[dy][dx + 1];
                    float xc = xv[dy + 1][dx], xd  = xv[dy + 1][dx + 1];
                    #pragma unroll
                    for (int jj = 0; jj < 6; jj++) {
                        float w = wp[jj * 76 + tap];
                        acc[jj][0] = fmaf(w, xa,  acc[jj][0]);
                        acc[jj][1] = fmaf(w, xb2, acc[jj][1]);
                        acc[jj][2] = fmaf(w, xc,  acc[jj][2]);
                        acc[jj][3] = fmaf(w, xd,  acc[jj][3]);
                    }
                }
            }
        }
    }

    float dtv = __ldg(dtp);
    int yb = y0 + py0, xb = x0 + px0;
    int pix[4] = { yb * 64 + xb, yb * 64 + xb + 1,
                   (yb + 1) * 64 + xb, (yb + 1) * 64 + xb + 1 };

    #pragma unroll
    for (int jj = 0; jj < 6; jj++) {
        int oc = oc0 + jj;
        if (oc < 64) {
            float bias = bd[oc] + dtv;
            float* dst = g_delta + (b * 64 + oc) * HW;
            #pragma unroll
            for (int q = 0; q < 4; q++) {
                float v = acc[jj][q] + bias;
                float sp = (v > 0.f) ? (v + log1pf(expf(-v))) : log1pf(expf(v));
                sp = fminf(fmaxf(sp, 1e-4f), 5.0f);
                dst[pix[q]] = sp;
            }
        } else if (oc < 80) {
            float* dst = g_Bval + (b * 16 + (oc - 64)) * HW;
            #pragma unroll
            for (int q = 0; q < 4; q++) dst[pix[q]] = acc[jj][q];
        } else {
            float* dst = g_Cval + (b * 16 + (oc - 80)) * HW;
            #pragma unroll
            for (int q = 0; q < 4; q++) dst[pix[q]] = acc[jj][q];
        }
    }
}

// ---------------------------------------------------------------------------
// K3: per-(b,d,n) plane: two circulant matmuls (grad_x, grad_y) via fp32x2,
// 8x8 register tiles, sliding h-window, fused state update -> s_new.
// 64 threads/block, 4096 blocks.
// ---------------------------------------------------------------------------
__global__ void __launch_bounds__(64) k_update(
        const float* __restrict__ u, const float* __restrict__ sprev,
        const float* __restrict__ logA, float* __restrict__ out) {
    __shared__ float Xs[64 * 65];    // X[r][c] at r*65 + c + (c>>5)
    __shared__ float hb[144];        // hb[i] = h[i mod 64]

    int tid = threadIdx.x;
    int bp  = blockIdx.x;            // b*1024 + d*16 + n
    int b = bp >> 10, d = (bp >> 4) & 63, n = bp & 15;

    int p0 = (((b * 3 + 0) * 64 + d) * 16 + n) * HW;
    int p1 = p0 + 64 * 16 * HW;
    int p2 = p1 + 64 * 16 * HW;
    const float* m0p = sprev + p0;

    #pragma unroll
    for (int l = tid; l < 4096; l += 64) {
        int r = l >> 6, c = l & 63;
        Xs[r * 65 + c + (c >> 5)] = m0p[l];
    }
    for (int i = tid; i < 144; i += 64) hb[i] = g_h[i & 63];
    __syncthreads();

    int rg = tid >> 3, cg = tid & 7;
    int r0 = rg * 8, c0 = cg * 8;
    int gap = c0 >> 5;

    float Ad = -expf(__ldg(&logA[d * 16 + n]));
    int off_bd = (b * 64 + d) * HW;
    int off_bn = (b * 16 + n) * HW;
    const int so = NB * DM * HW;

    // ===== Phase 1: Gx[r][c] = sum_k X[r][k] h[c-k], pack over row pairs =====
    {
        ull a[4][8];
        #pragma unroll
        for (int p = 0; p < 4; p++)
            #pragma unroll
            for (int j = 0; j < 8; j++) a[p][j] = 0ull;

        #pragma unroll 1
        for (int k8 = 0; k8 < 64; k8 += 8) {
            ull hl[15];
            int base = c0 - k8 + 57;
            #pragma unroll
            for (int m = 0; m < 15; m++) hl[m] = pk2(hb[base + m]);
            int gk = k8 >> 5;
            #pragma unroll
            for (int kk = 0; kk < 8; kk++) {
                int xo = k8 + kk + gk;
                float xv[8];
                #pragma unroll
                for (int i = 0; i < 8; i++) xv[i] = Xs[(r0 + i) * 65 + xo];
                ull xp4[4];
                #pragma unroll
                for (int p = 0; p < 4; p++) xp4[p] = pk(xv[2 * p], xv[2 * p + 1]);
                #pragma unroll
                for (int p = 0; p < 4; p++)
                    #pragma unroll
                    for (int j = 0; j < 8; j++)
                        fma2(a[p][j], xp4[p], hl[j - kk + 7]);
            }
        }

        // epilogue: m0_new, mx_new
        #pragma unroll
        for (int i = 0; i < 8; i++) {
            int row = r0 + i;
            int off = row * 64 + c0;
            float4 dv0 = *(const float4*)(g_delta + off_bd + off);
            float4 dv1 = *(const float4*)(g_delta + off_bd + off + 4);
            float4 uv0 = *(const float4*)(u + off_bd + off);
            float4 uv1 = *(const float4*)(u + off_bd + off + 4);
            float4 bv0 = *(const float4*)(g_Bval + off_bn + off);
            float4 bv1 = *(const float4*)(g_Bval + off_bn + off + 4);
            float4 mx0 = *(const float4*)(sprev + p1 + off);
            float4 mx1 = *(const float4*)(sprev + p1 + off + 4);
            float dd[8] = { dv0.x, dv0.y, dv0.z, dv0.w, dv1.x, dv1.y, dv1.z, dv1.w };
            float uu[8] = { uv0.x, uv0.y, uv0.z, uv0.w, uv1.x, uv1.y, uv1.z, uv1.w };
            float bb[8] = { bv0.x, bv0.y, bv0.z, bv0.w, bv1.x, bv1.y, bv1.z, bv1.w };
            float mx[8] = { mx0.x, mx0.y, mx0.z, mx0.w, mx1.x, mx1.y, mx1.z, mx1.w };
            float m0n[8], mxn[8];
            #pragma unroll
            for (int j = 0; j < 8; j++) {
                float2 t = up2(a[i >> 1][j]);
                float gx = (i & 1) ? t.y : t.x;
                float m0v = Xs[row * 65 + c0 + j + gap];
                float Ab = __expf(dd[j] * Ad);
                m0n[j] = fmaf(Ab, m0v, dd[j] * bb[j] * uu[j]);
                mxn[j] = Ab * (mx[j] - gx);
            }
            *(float4*)(out + so + p0 + off)     = make_float4(m0n[0], m0n[1], m0n[2], m0n[3]);
            *(float4*)(out + so + p0 + off + 4) = make_float4(m0n[4], m0n[5], m0n[6], m0n[7]);
            *(float4*)(out + so + p1 + off)     = make_float4(mxn[0], mxn[1], mxn[2], mxn[3]);
            *(float4*)(out + so + p1 + off + 4) = make_float4(mxn[4], mxn[5], mxn[6], mxn[7]);
        }
    }

    // ===== Phase 2: Gy[r][c] = sum_k h[r-k] X[k][c], pack over col pairs =====
    {
        ull g2[8][4];
        #pragma unroll
        for (int i = 0; i < 8; i++)
            #pragma unroll
            for (int q = 0; q < 4; q++) g2[i][q] = 0ull;

        #pragma unroll 1
        for (int k8 = 0; k8 < 64; k8 += 8) {
            ull gl[15];
            int base = r0 - k8 + 57;
            #pragma unroll
            for (int m = 0; m < 15; m++) gl[m] = pk2(hb[base + m]);
            #pragma unroll
            for (int kk = 0; kk < 8; kk++) {
                int ro = (k8 + kk) * 65 + c0 + gap;
                float xw[8];
                #pragma unroll
                for (int j = 0; j < 8; j++) xw[j] = Xs[ro + j];
                ull xq[4];
                #pragma unroll
                for (int q = 0; q < 4; q++) xq[q] = pk(xw[2 * q], xw[2 * q + 1]);
                #pragma unroll
                for (int i = 0; i < 8; i++)
                    #pragma unroll
                    for (int q = 0; q < 4; q++)
                        fma2(g2[i][q], gl[i - kk + 7], xq[q]);
            }
        }

        // epilogue: my_new
        #pragma unroll
        for (int i = 0; i < 8; i++) {
            int row = r0 + i;
            int off = row * 64 + c0;
            float4 dv0 = *(const float4*)(g_delta + off_bd + off);
            float4 dv1 = *(const float4*)(g_delta + off_bd + off + 4);
            float4 my0 = *(const float4*)(sprev + p2 + off);
            float4 my1 = *(const float4*)(sprev + p2 + off + 4);
            float dd[8] = { dv0.x, dv0.y, dv0.z, dv0.w, dv1.x, dv1.y, dv1.z, dv1.w };
            float my[8] = { my0.x, my0.y, my0.z, my0.w, my1.x, my1.y, my1.z, my1.w };
            float myn[8];
            #pragma unroll
            for (int j = 0; j < 8; j++) {
                float2 t = up2(g2[i][j >> 1]);
                float gy = (j & 1) ? t.y : t.x;
                float Ab = __expf(dd[j] * Ad);
                myn[j] = Ab * (my[j] - gy);
            }
            *(float4*)(out + so + p2 + off)     = make_float4(myn[0], myn[1], myn[2], myn[3]);
            *(float4*)(out + so + p2 + off + 4) = make_float4(myn[4], myn[5], myn[6], myn[7]);
        }
    }
}

// ---------------------------------------------------------------------------
// K4: y[b,d,p] = sum_n m0_new[b,d,n,p] * C_val[b,n,p] + u*D[d]
// ---------------------------------------------------------------------------
__global__ void k_y(const float* __restrict__ u, const float* __restrict__ Dp,
                    float* __restrict__ out) {
    int idx = blockIdx.x * 256 + threadIdx.x;   // < 1048576
    int b = idx >> 18;
    int d = (idx >> 12) & 63;
    int p = idx & 4095;
    const int so = NB * DM * HW;
    const float* m0n = out + so + ((b * 3 * 64 + d) * 16) * HW + p;
    const float* Cv  = g_Cval + (b * 16) * HW + p;
    float acc = 0.f;
    #pragma unroll
    for (int nn = 0; nn < 16; nn++)
        acc = fmaf(m0n[nn * HW], Cv[nn * HW], acc);
    out[idx] = fmaf(u[idx], Dp[d], acc);
}

// ---------------------------------------------------------------------------
extern "C" void kernel_launch(void* const* d_in, const int* in_sizes, int n_in,
                              void* d_out, int out_size) {
    const float* u     = (const float*)d_in[0];
    const float* sprev = (const float*)d_in[1];
    const float* gamma = (const float*)d_in[2];
    const float* beta  = (const float*)d_in[3];
    const float* wd    = (const float*)d_in[4];
    const float* bd    = (const float*)d_in[5];
    const float* wB    = (const float*)d_in[6];
    const float* wC    = (const float*)d_in[7];
    const float* logA  = (const float*)d_in[8];
    const float* Dp    = (const float*)d_in[9];
    const float* dt    = (const float*)d_in[10];
    float* out = (float*)d_out;

    k_init_h<<<1, 64>>>();
    k_stats<<<16, 1024>>>(u);
    k_conv<<<512, 128>>>(u, gamma, beta, wd, bd, wB, wC, dt);
    k_update<<<4096, 64>>>(u, sprev, logA, out);
    k_y<<<4096, 256>>>(u, Dp, out);
}

// round 6
// speedup vs baseline: 1.6443x; 1.0584x over previous
#include <cuda_runtime.h>
#include <math.h>

#define HW    4096
#define DM    64
#define DS    16
#define NB    4

// Scratch (device globals; no allocation allowed)
__device__ float g_h[64];
__device__ float g_part[512];         // 256 blocks x (sum, sumsq)
__device__ float g_delta[NB*DM*HW];   // 4MB
__device__ float g_Bval[NB*DS*HW];    // 1MB
__device__ float g_Cval[NB*DS*HW];    // 1MB

typedef unsigned long long ull;

__device__ __forceinline__ ull pk2(float x) {
    ull r; asm("mov.b64 %0,{%1,%1};" : "=l"(r) : "f"(x)); return r;
}
__device__ __forceinline__ ull pk(float lo, float hi) {
    ull r; asm("mov.b64 %0,{%1,%2};" : "=l"(r) : "f"(lo), "f"(hi)); return r;
}
__device__ __forceinline__ void fma2(ull &a, ull b, ull c) {
    asm("fma.rn.f32x2 %0,%1,%2,%0;" : "+l"(a) : "l"(b), "l"(c));
}
__device__ __forceinline__ float2 up2(ull a) {
    float2 v; asm("mov.b64 {%0,%1},%2;" : "=f"(v.x), "=f"(v.y) : "l"(a)); return v;
}
template<int N> __device__ __forceinline__ void cpwait() {
    asm volatile("cp.async.wait_group %0;" :: "n"(N));
}

// ---------------------------------------------------------------------------
// K0: spectral-derivative circular kernel h[n] (exact, fp64 accumulation)
// ---------------------------------------------------------------------------
__global__ void k_init_h() {
    int n = threadIdx.x;  // 0..63
    double acc = 0.0;
    for (int m = 1; m < 32; m++) {
        double km = 2.0 * 3.141592653589793238 * (double)m / 64.0;
        acc += km * sin(km * (double)n);
    }
    g_h[n] = (float)(-acc * 2.0 / 64.0);
}

// ---------------------------------------------------------------------------
// K1: GroupNorm partial sums. 256 blocks (16 per (b,g)), deterministic.
// ---------------------------------------------------------------------------
__global__ void __launch_bounds__(256) k_stats(const float* __restrict__ u) {
    int blk = blockIdx.x;
    int bg = blk >> 4, seg = blk & 15;
    const float4* base = (const float4*)(u + bg * 65536 + seg * 4096);
    float s = 0.f, s2 = 0.f;
    #pragma unroll
    for (int i = threadIdx.x; i < 1024; i += 256) {
        float4 v = base[i];
        s += v.x + v.y + v.z + v.w;
        s2 = fmaf(v.x, v.x, s2); s2 = fmaf(v.y, v.y, s2);
        s2 = fmaf(v.z, v.z, s2); s2 = fmaf(v.w, v.w, s2);
    }
    for (int o = 16; o; o >>= 1) {
        s  += __shfl_down_sync(0xFFFFFFFFu, s,  o);
        s2 += __shfl_down_sync(0xFFFFFFFFu, s2, o);
    }
    __shared__ float ss[8], ss2[8];
    int w = threadIdx.x >> 5, l = threadIdx.x & 31;
    if (l == 0) { ss[w] = s; ss2[w] = s2; }
    __syncthreads();
    if (threadIdx.x == 0) {
        float S = 0.f, S2 = 0.f;
        #pragma unroll
        for (int i = 0; i < 8; i++) { S += ss[i]; S2 += ss2[i]; }
        g_part[blk * 2]     = S;
        g_part[blk * 2 + 1] = S2;
    }
}

// ---------------------------------------------------------------------------
// K2: fused GroupNorm + circular 3x3 convs: 96 oc (64 delta | 16 B | 16 C).
// Grid 512 = 4b x 128 tiles (8x4). 128 thr = 16 ocg x 8 pxg; thread 6oc x 2x2.
// Full 64-ch halo resident; weights double-buffered via cp.async (4-ic chunks).
// ---------------------------------------------------------------------------
__global__ void __launch_bounds__(128) k_conv(
        const float* __restrict__ u,
        const float* __restrict__ gamma, const float* __restrict__ beta,
        const float* __restrict__ wd, const float* __restrict__ bd,
        const float* __restrict__ wB, const float* __restrict__ wC,
        const float* __restrict__ dtp) {
    __shared__ float ws[2 * 96 * 36];    // [buf][oc][icl(4) x tap(9)] 27.6KB
    __shared__ float xs[64 * 60];        // [ch][10 rows][6 cols] 15.4KB
    __shared__ float cs_scale[64], cs_shift[64];

    int bx = blockIdx.x;
    int b  = bx >> 7;
    int t  = bx & 127;
    int y0 = (t >> 4) * 8;
    int x0 = (t & 15) * 4;

    int tid = threadIdx.x;
    int ocg = tid >> 3;            // 0..15
    int pxg = tid & 7;             // 0..7
    int oc0 = ocg * 6;
    int py0 = (pxg >> 1) * 2;      // 0,2,4,6
    int px0 = (pxg & 1) * 2;       // 0,2

    // finalize GroupNorm stats from partials
    if (tid < 64) {
        int bg = b * 4 + (tid >> 4);
        float S = 0.f, S2 = 0.f;
        #pragma unroll
        for (int i = 0; i < 16; i++) {
            S  += g_part[(bg * 16 + i) * 2];
            S2 += g_part[(bg * 16 + i) * 2 + 1];
        }
        float mu  = S  * (1.f / 65536.f);
        float var = S2 * (1.f / 65536.f) - mu * mu;
        float rs = rsqrtf(var + 1e-5f) * gamma[tid];
        cs_scale[tid] = rs;
        cs_shift[tid] = beta[tid] - mu * rs;
    }
    __syncthreads();

    unsigned ws_sm = (unsigned)__cvta_generic_to_shared(ws);

    // issue chunk 0 weights (4 ic = 9 float4 per oc)
    {
        #pragma unroll 1
        for (int l4 = tid; l4 < 864; l4 += 128) {
            int oc = l4 / 9, rem = l4 - oc * 9;
            const float4* src;
            if (oc < 64)      src = (const float4*)wd + oc * 144 + rem;
            else if (oc < 80) src = (const float4*)wB + (oc - 64) * 144 + rem;
            else              src = (const float4*)wC + (oc - 80) * 144 + rem;
            unsigned dst = ws_sm + (oc * 36 + rem * 4) * 4;
            asm volatile("cp.async.cg.shared.global [%0], [%1], 16;" :: "r"(dst), "l"(src));
        }
        asm volatile("cp.async.commit_group;");
    }

    // normalized halo for all 64 channels: 64 x 10 x 6
    #pragma unroll 1
    for (int l = tid; l < 3840; l += 128) {
        int icl = l / 60; int r = l - icl * 60;
        int yy = r / 6, xx = r - yy * 6;
        int gy = (y0 + yy - 1) & 63;
        int gx = (x0 + xx - 1) & 63;
        float v = u[((b * 64 + icl) * 64 + gy) * 64 + gx];
        xs[l] = fmaf(v, cs_scale[icl], cs_shift[icl]);
    }

    float acc[6][4];
    #pragma unroll
    for (int j = 0; j < 6; j++)
        #pragma unroll
        for (int q = 0; q < 4; q++) acc[j][q] = 0.f;

    cpwait<0>();
    __syncthreads();

    #pragma unroll 1
    for (int c = 0; c < 16; c++) {
        if (c < 15) {
            int nc = c + 1, buf = nc & 1;
            #pragma unroll 1
            for (int l4 = tid; l4 < 864; l4 += 128) {
                int oc = l4 / 9, rem = l4 - oc * 9;
                const float4* src;
                if (oc < 64)      src = (const float4*)wd + oc * 144 + nc * 9 + rem;
                else if (oc < 80) src = (const float4*)wB + (oc - 64) * 144 + nc * 9 + rem;
                else              src = (const float4*)wC + (oc - 80) * 144 + nc * 9 + rem;
                unsigned dst = ws_sm + (buf * 3456 + oc * 36 + rem * 4) * 4;
                asm volatile("cp.async.cg.shared.global [%0], [%1], 16;" :: "r"(dst), "l"(src));
            }
            asm volatile("cp.async.commit_group;");
            cpwait<1>();
        } else {
            cpwait<0>();
        }
        __syncthreads();

        const float* wsb = ws + (c & 1) * 3456;
        #pragma unroll
        for (int icl = 0; icl < 4; icl++) {
            int ic = c * 4 + icl;
            const float* wp = wsb + oc0 * 36 + icl * 9;
            const float* xp = xs + ic * 60 + py0 * 6 + px0;
            float xv[4][4];
            #pragma unroll
            for (int rr = 0; rr < 4; rr++)
                #pragma unroll
                for (int cc = 0; cc < 4; cc++) xv[rr][cc] = xp[rr * 6 + cc];
            #pragma unroll
            for (int dy = 0; dy < 3; dy++) {
                #pragma unroll
                for (int dx = 0; dx < 3; dx++) {
                    int tap = dy * 3 + dx;
                    float xa = xv[dy][dx],     xb2 = xv[dy][dx + 1];
                    float xc = xv[dy + 1][dx], xd  = xv[dy + 1][dx + 1];
                    #pragma unroll
                    for (int jj = 0; jj < 6; jj++) {
                        float w = wp[jj * 36 + tap];
                        acc[jj][0] = fmaf(w, xa,  acc[jj][0]);
                        acc[jj][1] = fmaf(w, xb2, acc[jj][1]);
                        acc[jj][2] = fmaf(w, xc,  acc[jj][2]);
                        acc[jj][3] = fmaf(w, xd,  acc[jj][3]);
                    }
                }
            }
        }
        __syncthreads();
    }

    float dtv = __ldg(dtp);
    int yb = y0 + py0, xb = x0 + px0;
    int pix[4] = { yb * 64 + xb, yb * 64 + xb + 1,
                   (yb + 1) * 64 + xb, (yb + 1) * 64 + xb + 1 };

    #pragma unroll
    for (int jj = 0; jj < 6; jj++) {
        int oc = oc0 + jj;
        if (oc < 64) {
            float bias = bd[oc] + dtv;
            float* dst = g_delta + (b * 64 + oc) * HW;
            #pragma unroll
            for (int q = 0; q < 4; q++) {
                float v = acc[jj][q] + bias;
                float sp = (v > 0.f) ? (v + log1pf(expf(-v))) : log1pf(expf(v));
                sp = fminf(fmaxf(sp, 1e-4f), 5.0f);
                dst[pix[q]] = sp;
            }
        } else if (oc < 80) {
            float* dst = g_Bval + (b * 16 + (oc - 64)) * HW;
            #pragma unroll
            for (int q = 0; q < 4; q++) dst[pix[q]] = acc[jj][q];
        } else {
            float* dst = g_Cval + (b * 16 + (oc - 80)) * HW;
            #pragma unroll
            for (int q = 0; q < 4; q++) dst[pix[q]] = acc[jj][q];
        }
    }
}

// ---------------------------------------------------------------------------
// K3: per-(b,d,n) plane: two circulant matmuls (grad_x, grad_y) via fp32x2,
// 4x8 register tiles, sliding h-window, fused state update -> s_new.
// 128 threads/block, 4096 blocks. X swizzled stride-68 (2-float gap @ c=32)
// so phase-2 row reads are aligned 64-bit LDS.
// ---------------------------------------------------------------------------
__global__ void __launch_bounds__(128, 3) k_update(
        const float* __restrict__ u, const float* __restrict__ sprev,
        const float* __restrict__ logA, float* __restrict__ out) {
    __shared__ float Xs[64 * 68];    // X[r][c] at r*68 + c + 2*(c>>5)
    __shared__ float hb[144];        // hb[i] = h[i mod 64]

    int tid = threadIdx.x;
    int bp  = blockIdx.x;            // b*1024 + d*16 + n
    int b = bp >> 10, d = (bp >> 4) & 63, n = bp & 15;

    int p0 = (((b * 3 + 0) * 64 + d) * 16 + n) * HW;
    int p1 = p0 + 64 * 16 * HW;
    int p2 = p1 + 64 * 16 * HW;
    const float* m0p = sprev + p0;

    #pragma unroll
    for (int l = tid; l < 4096; l += 128) {
        int r = l >> 6, c = l & 63;
        Xs[r * 68 + c + 2 * (c >> 5)] = m0p[l];
    }
    for (int i = tid; i < 144; i += 128) hb[i] = g_h[i & 63];
    __syncthreads();

    int rg = tid >> 3, cg = tid & 7;    // rg 0..15, cg 0..7
    int r0 = rg * 4, c0 = cg * 8;
    int gap2 = 2 * (c0 >> 5);

    float Ad = -expf(__ldg(&logA[d * 16 + n]));
    int off_bd = (b * 64 + d) * HW;
    int off_bn = (b * 16 + n) * HW;
    const int so = NB * DM * HW;

    // ===== Phase 1: Gx[r][c] = sum_k X[r][k] h[c-k], pack over row pairs ====
    {
        ull a[2][8];
        #pragma unroll
        for (int p = 0; p < 2; p++)
            #pragma unroll
            for (int j = 0; j < 8; j++) a[p][j] = 0ull;

        #pragma unroll 1
        for (int k8 = 0; k8 < 64; k8 += 8) {
            ull hl[15];
            int base = c0 - k8 + 57;
            #pragma unroll
            for (int m = 0; m < 15; m++) hl[m] = pk2(hb[base + m]);
            int gk = 2 * (k8 >> 5);
            #pragma unroll
            for (int kk = 0; kk < 8; kk++) {
                int xo = k8 + kk + gk;
                float xv[4];
                #pragma unroll
                for (int i = 0; i < 4; i++) xv[i] = Xs[(r0 + i) * 68 + xo];
                ull xp2[2] = { pk(xv[0], xv[1]), pk(xv[2], xv[3]) };
                #pragma unroll
                for (int p = 0; p < 2; p++)
                    #pragma unroll
                    for (int j = 0; j < 8; j++)
                        fma2(a[p][j], xp2[p], hl[j - kk + 7]);
            }
        }

        // epilogue: m0_new, mx_new
        #pragma unroll
        for (int i = 0; i < 4; i++) {
            int row = r0 + i;
            int off = row * 64 + c0;
            float4 dv0 = *(const float4*)(g_delta + off_bd + off);
            float4 dv1 = *(const float4*)(g_delta + off_bd + off + 4);
            float4 uv0 = *(const float4*)(u + off_bd + off);
            float4 uv1 = *(const float4*)(u + off_bd + off + 4);
            float4 bv0 = *(const float4*)(g_Bval + off_bn + off);
            float4 bv1 = *(const float4*)(g_Bval + off_bn + off + 4);
            float4 mx0 = *(const float4*)(sprev + p1 + off);
            float4 mx1 = *(const float4*)(sprev + p1 + off + 4);
            float dd[8] = { dv0.x, dv0.y, dv0.z, dv0.w, dv1.x, dv1.y, dv1.z, dv1.w };
            float uu[8] = { uv0.x, uv0.y, uv0.z, uv0.w, uv1.x, uv1.y, uv1.z, uv1.w };
            float bb[8] = { bv0.x, bv0.y, bv0.z, bv0.w, bv1.x, bv1.y, bv1.z, bv1.w };
            float mx[8] = { mx0.x, mx0.y, mx0.z, mx0.w, mx1.x, mx1.y, mx1.z, mx1.w };
            float m0n[8], mxn[8];
            #pragma unroll
            for (int j = 0; j < 8; j++) {
                float2 t = up2(a[i >> 1][j]);
                float gx = (i & 1) ? t.y : t.x;
                float m0v = Xs[row * 68 + c0 + j + gap2];
                float Ab = __expf(dd[j] * Ad);
                m0n[j] = fmaf(Ab, m0v, dd[j] * bb[j] * uu[j]);
                mxn[j] = Ab * (mx[j] - gx);
            }
            *(float4*)(out + so + p0 + off)     = make_float4(m0n[0], m0n[1], m0n[2], m0n[3]);
            *(float4*)(out + so + p0 + off + 4) = make_float4(m0n[4], m0n[5], m0n[6], m0n[7]);
            *(float4*)(out + so + p1 + off)     = make_float4(mxn[0], mxn[1], mxn[2], mxn[3]);
            *(float4*)(out + so + p1 + off + 4) = make_float4(mxn[4], mxn[5], mxn[6], mxn[7]);
        }
    }

    // ===== Phase 2: Gy[r][c] = sum_k h[r-k] X[k][c], pack over col pairs ====
    {
        ull g2[4][4];
        #pragma unroll
        for (int i = 0; i < 4; i++)
            #pragma unroll
            for (int q = 0; q < 4; q++) g2[i][q] = 0ull;

        #pragma unroll 1
        for (int k8 = 0; k8 < 64; k8 += 8) {
            ull gl[11];
            int base = r0 - k8 + 57;
            #pragma unroll
            for (int m = 0; m < 11; m++) gl[m] = pk2(hb[base + m]);
            #pragma unroll
            for (int kk = 0; kk < 8; kk++) {
                int ro = (k8 + kk) * 68 + c0 + gap2;   // even -> 8B aligned
                const ull* xrow = (const ull*)&Xs[ro];
                ull xq[4];
                #pragma unroll
                for (int q = 0; q < 4; q++) xq[q] = xrow[q];
                #pragma unroll
                for (int i = 0; i < 4; i++)
                    #pragma unroll
                    for (int q = 0; q < 4; q++)
                        fma2(g2[i][q], gl[i - kk + 7], xq[q]);
            }
        }

        // epilogue: my_new
        #pragma unroll
        for (int i = 0; i < 4; i++) {
            int row = r0 + i;
            int off = row * 64 + c0;
            float4 dv0 = *(const float4*)(g_delta + off_bd + off);
            float4 dv1 = *(const float4*)(g_delta + off_bd + off + 4);
            float4 my0 = *(const float4*)(sprev + p2 + off);
            float4 my1 = *(const float4*)(sprev + p2 + off + 4);
            float dd[8] = { dv0.x, dv0.y, dv0.z, dv0.w, dv1.x, dv1.y, dv1.z, dv1.w };
            float my[8] = { my0.x, my0.y, my0.z, my0.w, my1.x, my1.y, my1.z, my1.w };
            float myn[8];
            #pragma unroll
            for (int j = 0; j < 8; j++) {
                float2 t = up2(g2[i][j >> 1]);
                float gy = (j & 1) ? t.y : t.x;
                float Ab = __expf(dd[j] * Ad);
                myn[j] = Ab * (my[j] - gy);
            }
            *(float4*)(out + so + p2 + off)     = make_float4(myn[0], myn[1], myn[2], myn[3]);
            *(float4*)(out + so + p2 + off + 4) = make_float4(myn[4], myn[5], myn[6], myn[7]);
        }
    }
}

// ---------------------------------------------------------------------------
// K4: y[b,d,p] = sum_n m0_new[b,d,n,p] * C_val[b,n,p] + u*D[d]
// ---------------------------------------------------------------------------
__global__ void k_y(const float* __restrict__ u, const float* __restrict__ Dp,
                    float* __restrict__ out) {
    int idx = blockIdx.x * 256 + threadIdx.x;   // < 1048576
    int b = idx >> 18;
    int d = (idx >> 12) & 63;
    int p = idx & 4095;
    const int so = NB * DM * HW;
    const float* m0n = out + so + ((b * 3 * 64 + d) * 16) * HW + p;
    const float* Cv  = g_Cval + (b * 16) * HW + p;
    float acc = 0.f;
    #pragma unroll
    for (int nn = 0; nn < 16; nn++)
        acc = fmaf(m0n[nn * HW], Cv[nn * HW], acc);
    out[idx] = fmaf(u[idx], Dp[d], acc);
}

// ---------------------------------------------------------------------------
extern "C" void kernel_launch(void* const* d_in, const int* in_sizes, int n_in,
                              void* d_out, int out_size) {
    const float* u     = (const float*)d_in[0];
    const float* sprev = (const float*)d_in[1];
    const float* gamma = (const float*)d_in[2];
    const float* beta  = (const float*)d_in[3];
    const float* wd    = (const float*)d_in[4];
    const float* bd    = (const float*)d_in[5];
    const float* wB    = (const float*)d_in[6];
    const float* wC    = (const float*)d_in[7];
    const float* logA  = (const float*)d_in[8];
    const float* Dp    = (const float*)d_in[9];
    const float* dt    = (const float*)d_in[10];
    float* out = (float*)d_out;

    k_init_h<<<1, 64>>>();
    k_stats<<<256, 256>>>(u);
    k_conv<<<512, 128>>>(u, gamma, beta, wd, bd, wB, wC, dt);
    k_update<<<4096, 128>>>(u, sprev, logA, out);
    k_y<<<4096, 256>>>(u, Dp, out);
}

// round 8
// speedup vs baseline: 1.6638x; 1.0118x over previous
#include <cuda_runtime.h>
#include <math.h>

#define HW    4096
#define DM    64
#define DS    16
#define NB    4

// Scratch (device globals; no allocation allowed)
__device__ float g_h[64];
__device__ float g_part[512];         // 256 blocks x (sum, sumsq)
__device__ float g_delta[NB*DM*HW];   // 4MB
__device__ float g_Bval[NB*DS*HW];    // 1MB
__device__ float g_Cval[NB*DS*HW];    // 1MB

typedef unsigned long long ull;

__device__ __forceinline__ ull pk2(float x) {
    ull r; asm("mov.b64 %0,{%1,%1};" : "=l"(r) : "f"(x)); return r;
}
__device__ __forceinline__ ull pk(float lo, float hi) {
    ull r; asm("mov.b64 %0,{%1,%2};" : "=l"(r) : "f"(lo), "f"(hi)); return r;
}
__device__ __forceinline__ void fma2(ull &a, ull b, ull c) {
    asm("fma.rn.f32x2 %0,%1,%2,%0;" : "+l"(a) : "l"(b), "l"(c));
}
__device__ __forceinline__ float2 up2(ull a) {
    float2 v; asm("mov.b64 {%0,%1},%2;" : "=f"(v.x), "=f"(v.y) : "l"(a)); return v;
}

// ---------------------------------------------------------------------------
// K0: spectral-derivative circular kernel h[n] (exact, fp64 accumulation)
// ---------------------------------------------------------------------------
__global__ void k_init_h() {
    int n = threadIdx.x;  // 0..63
    double acc = 0.0;
    for (int m = 1; m < 32; m++) {
        double km = 2.0 * 3.141592653589793238 * (double)m / 64.0;
        acc += km * sin(km * (double)n);
    }
    g_h[n] = (float)(-acc * 2.0 / 64.0);
}

// ---------------------------------------------------------------------------
// K1: GroupNorm partial sums. 256 blocks (16 per (b,g)), deterministic.
// ---------------------------------------------------------------------------
__global__ void __launch_bounds__(256) k_stats(const float* __restrict__ u) {
    int blk = blockIdx.x;
    int bg = blk >> 4, seg = blk & 15;
    const float4* base = (const float4*)(u + bg * 65536 + seg * 4096);
    float s = 0.f, s2 = 0.f;
    #pragma unroll
    for (int i = threadIdx.x; i < 1024; i += 256) {
        float4 v = base[i];
        s += v.x + v.y + v.z + v.w;
        s2 = fmaf(v.x, v.x, s2); s2 = fmaf(v.y, v.y, s2);
        s2 = fmaf(v.z, v.z, s2); s2 = fmaf(v.w, v.w, s2);
    }
    for (int o = 16; o; o >>= 1) {
        s  += __shfl_down_sync(0xFFFFFFFFu, s,  o);
        s2 += __shfl_down_sync(0xFFFFFFFFu, s2, o);
    }
    __shared__ float ss[8], ss2[8];
    int w = threadIdx.x >> 5, l = threadIdx.x & 31;
    if (l == 0) { ss[w] = s; ss2[w] = s2; }
    __syncthreads();
    if (threadIdx.x == 0) {
        float S = 0.f, S2 = 0.f;
        #pragma unroll
        for (int i = 0; i < 8; i++) { S += ss[i]; S2 += ss2[i]; }
        g_part[blk * 2]     = S;
        g_part[blk * 2 + 1] = S2;
    }
}

// ---------------------------------------------------------------------------
// K2: fused GroupNorm + circular 3x3 convs, packed f32x2 over oc pairs.
// Grid 512 = 4b x 128 tiles (8x4). 128 thr = 16 ocg x 8 pxg; thread 6oc x 2x2.
// Weights staged transposed [tap_icl][oc] (stride 98), double-buffered
// via LDG->reg->STS. Full 64-ch normalized halo resident.
// ---------------------------------------------------------------------------
#define WST 98
__global__ void __launch_bounds__(128) k_conv(
        const float* __restrict__ u,
        const float* __restrict__ gamma, const float* __restrict__ beta,
        const float* __restrict__ wd, const float* __restrict__ bd,
        const float* __restrict__ wB, const float* __restrict__ wC,
        const float* __restrict__ dtp) {
    __shared__ float ws2[2][36 * WST];   // 28.2KB: [buf][icl*9+tap][oc]
    __shared__ float xs[64 * 60];        // [ch][10 rows][6 cols] 15.4KB
    __shared__ float cs_scale[64], cs_shift[64];

    int bx = blockIdx.x;
    int b  = bx >> 7;
    int t  = bx & 127;
    int y0 = (t >> 4) * 8;
    int x0 = (t & 15) * 4;

    int tid = threadIdx.x;
    int ocg = tid >> 3;            // 0..15
    int pxg = tid & 7;             // 0..7
    int oc0 = ocg * 6;
    int py0 = (pxg >> 1) * 2;      // 0,2,4,6
    int px0 = (pxg & 1) * 2;       // 0,2

    // finalize GroupNorm stats from partials
    if (tid < 64) {
        int bg = b * 4 + (tid >> 4);
        float S = 0.f, S2 = 0.f;
        #pragma unroll
        for (int i = 0; i < 16; i++) {
            S  += g_part[(bg * 16 + i) * 2];
            S2 += g_part[(bg * 16 + i) * 2 + 1];
        }
        float mu  = S  * (1.f / 65536.f);
        float var = S2 * (1.f / 65536.f) - mu * mu;
        float rs = rsqrtf(var + 1e-5f) * gamma[tid];
        cs_scale[tid] = rs;
        cs_shift[tid] = beta[tid] - mu * rs;
    }
    __syncthreads();

    // per-thread LDG slots: l4 = tid + 128*s, s<7, valid if l4 < 864
    int l_oc[7], l_rem[7];
    #pragma unroll
    for (int s = 0; s < 7; s++) {
        int l4 = tid + 128 * s;
        l_oc[s]  = l4 / 9;
        l_rem[s] = l4 - l_oc[s] * 9;
    }
    float4 rg[7];

    // LDG chunk 0
    #pragma unroll
    for (int s = 0; s < 7; s++) {
        if (tid + 128 * s < 864) {
            int oc = l_oc[s], rem = l_rem[s];
            const float4* src;
            if (oc < 64)      src = (const float4*)wd + oc * 144 + rem;
            else if (oc < 80) src = (const float4*)wB + (oc - 64) * 144 + rem;
            else              src = (const float4*)wC + (oc - 80) * 144 + rem;
            rg[s] = __ldg(src);
        }
    }

    // normalized halo for all 64 channels: 64 x 10 x 6
    #pragma unroll 1
    for (int l = tid; l < 3840; l += 128) {
        int icl = l / 60; int r = l - icl * 60;
        int yy = r / 6, xx = r - yy * 6;
        int gy = (y0 + yy - 1) & 63;
        int gx = (x0 + xx - 1) & 63;
        float v = u[((b * 64 + icl) * 64 + gy) * 64 + gx];
        xs[l] = fmaf(v, cs_scale[icl], cs_shift[icl]);
    }

    // STS chunk 0 (transposed)
    #pragma unroll
    for (int s = 0; s < 7; s++) {
        if (tid + 128 * s < 864) {
            int oc = l_oc[s], rem = l_rem[s];
            ws2[0][(rem * 4 + 0) * WST + oc] = rg[s].x;
            ws2[0][(rem * 4 + 1) * WST + oc] = rg[s].y;
            ws2[0][(rem * 4 + 2) * WST + oc] = rg[s].z;
            ws2[0][(rem * 4 + 3) * WST + oc] = rg[s].w;
        }
    }
    __syncthreads();

    ull acc[3][4];   // oc pairs (oc0+2p, oc0+2p+1) x 4 px
    #pragma unroll
    for (int p = 0; p < 3; p++)
        #pragma unroll
        for (int q = 0; q < 4; q++) acc[p][q] = 0ull;

    #pragma unroll 1
    for (int c = 0; c < 16; c++) {
        if (c < 15) {
            int nc = c + 1;
            #pragma unroll
            for (int s = 0; s < 7; s++) {
                if (tid + 128 * s < 864) {
                    int oc = l_oc[s], rem = l_rem[s];
                    const float4* src;
                    if (oc < 64)      src = (const float4*)wd + oc * 144 + nc * 9 + rem;
                    else if (oc < 80) src = (const float4*)wB + (oc - 64) * 144 + nc * 9 + rem;
                    else              src = (const float4*)wC + (oc - 80) * 144 + nc * 9 + rem;
                    rg[s] = __ldg(src);
                }
            }
        }

        const float* wsb = ws2[c & 1];
        #pragma unroll
        for (int icl = 0; icl < 4; icl++) {
            int ic = c * 4 + icl;
            const float* xp = xs + ic * 60 + py0 * 6 + px0;
            float xr[4][4];
            #pragma unroll
            for (int rr = 0; rr < 4; rr++) {
                float2 lo = *(const float2*)(xp + rr * 6);
                float2 hi = *(const float2*)(xp + rr * 6 + 2);
                xr[rr][0] = lo.x; xr[rr][1] = lo.y;
                xr[rr][2] = hi.x; xr[rr][3] = hi.y;
            }
            #pragma unroll
            for (int dy = 0; dy < 3; dy++) {
                #pragma unroll
                for (int dx = 0; dx < 3; dx++) {
                    const float* row = wsb + (icl * 9 + dy * 3 + dx) * WST + oc0;
                    ull w01 = *(const ull*)(row);
                    ull w23 = *(const ull*)(row + 2);
                    ull w45 = *(const ull*)(row + 4);
                    ull pa = pk2(xr[dy][dx]);
                    ull pb = pk2(xr[dy][dx + 1]);
                    ull pc = pk2(xr[dy + 1][dx]);
                    ull pd = pk2(xr[dy + 1][dx + 1]);
                    fma2(acc[0][0], w01, pa); fma2(acc[0][1], w01, pb);
                    fma2(acc[0][2], w01, pc); fma2(acc[0][3], w01, pd);
                    fma2(acc[1][0], w23, pa); fma2(acc[1][1], w23, pb);
                    fma2(acc[1][2], w23, pc); fma2(acc[1][3], w23, pd);
                    fma2(acc[2][0], w45, pa); fma2(acc[2][1], w45, pb);
                    fma2(acc[2][2], w45, pc); fma2(acc[2][3], w45, pd);
                }
            }
        }

        if (c < 15) {
            float* dstb = ws2[(c + 1) & 1];
            #pragma unroll
            for (int s = 0; s < 7; s++) {
                if (tid + 128 * s < 864) {
                    int oc = l_oc[s], rem = l_rem[s];
                    dstb[(rem * 4 + 0) * WST + oc] = rg[s].x;
                    dstb[(rem * 4 + 1) * WST + oc] = rg[s].y;
                    dstb[(rem * 4 + 2) * WST + oc] = rg[s].z;
                    dstb[(rem * 4 + 3) * WST + oc] = rg[s].w;
                }
            }
        }
        __syncthreads();
    }

    float dtv = __ldg(dtp);
    int yb = y0 + py0, xb = x0 + px0;
    int pix[4] = { yb * 64 + xb, yb * 64 + xb + 1,
                   (yb + 1) * 64 + xb, (yb + 1) * 64 + xb + 1 };

    #pragma unroll
    for (int p = 0; p < 3; p++) {
        #pragma unroll
        for (int half = 0; half < 2; half++) {
            int oc = oc0 + 2 * p + half;
            float av[4];
            #pragma unroll
            for (int q = 0; q < 4; q++) {
                float2 v = up2(acc[p][q]);
                av[q] = half ? v.y : v.x;
            }
            if (oc < 64) {
                float bias = bd[oc] + dtv;
                float* dst = g_delta + (b * 64 + oc) * HW;
                #pragma unroll
                for (int q = 0; q < 4; q++) {
                    float v = av[q] + bias;
                    float sp = (v > 0.f) ? (v + log1pf(expf(-v))) : log1pf(expf(v));
                    sp = fminf(fmaxf(sp, 1e-4f), 5.0f);
                    dst[pix[q]] = sp;
                }
            } else if (oc < 80) {
                float* dst = g_Bval + (b * 16 + (oc - 64)) * HW;
                #pragma unroll
                for (int q = 0; q < 4; q++) dst[pix[q]] = av[q];
            } else {
                float* dst = g_Cval + (b * 16 + (oc - 80)) * HW;
                #pragma unroll
                for (int q = 0; q < 4; q++) dst[pix[q]] = av[q];
            }
        }
    }
}

// ---------------------------------------------------------------------------
// K3: per-(b,d,n) plane: two circulant matmuls (grad_x, grad_y) via fp32x2,
// 4x8 register tiles, sliding h-window w/ register rotation, float2 X loads,
// A_bar carried in registers across phases. 128 thr, 4096 blocks.
// ---------------------------------------------------------------------------
__global__ void __launch_bounds__(128, 3) k_update(
        const float* __restrict__ u, const float* __restrict__ sprev,
        const float* __restrict__ logA, float* __restrict__ out) {
    __shared__ float Xs[64 * 68];    // X[r][c] at r*68 + c + 2*(c>>5)
    __shared__ float hb[144];        // hb[i] = h[i mod 64]

    int tid = threadIdx.x;
    int bp  = blockIdx.x;            // b*1024 + d*16 + n
    int b = bp >> 10, d = (bp >> 4) & 63, n = bp & 15;

    int p0 = (((b * 3 + 0) * 64 + d) * 16 + n) * HW;
    int p1 = p0 + 64 * 16 * HW;
    int p2 = p1 + 64 * 16 * HW;
    const float* m0p = sprev + p0;

    #pragma unroll
    for (int l = tid; l < 4096; l += 128) {
        int r = l >> 6, c = l & 63;
        Xs[r * 68 + c + 2 * (c >> 5)] = m0p[l];
    }
    for (int i = tid; i < 144; i += 128) hb[i] = g_h[i & 63];
    __syncthreads();

    int rg = tid >> 3, cg = tid & 7;    // rg 0..15, cg 0..7
    int r0 = rg * 4, c0 = cg * 8;
    int gap2 = 2 * (c0 >> 5);

    float Ad = -expf(__ldg(&logA[d * 16 + n]));
    int off_bd = (b * 64 + d) * HW;
    int off_bn = (b * 16 + n) * HW;
    const int so = NB * DM * HW;

    float Abs[32];   // A_bar carried into phase 2

    // ===== Phase 1: Gx[r][c] = sum_k X[r][k] h[c-k], pack over row pairs ====
    {
        ull a[2][8];
        #pragma unroll
        for (int p = 0; p < 2; p++)
            #pragma unroll
            for (int j = 0; j < 8; j++) a[p][j] = 0ull;

        ull hl[15];
        #pragma unroll
        for (int m = 0; m < 15; m++) hl[m] = pk2(hb[c0 + 57 + m]);

        #pragma unroll 1
        for (int k8 = 0; k8 < 64; k8 += 8) {
            int gk = 2 * (k8 >> 5);
            #pragma unroll
            for (int kk2 = 0; kk2 < 4; kk2++) {
                int xo = k8 + kk2 * 2 + gk;
                float2 xr[4];
                #pragma unroll
                for (int i = 0; i < 4; i++)
                    xr[i] = *(const float2*)&Xs[(r0 + i) * 68 + xo];
                // kk = 2*kk2 (lo halves)
                {
                    int kk = kk2 * 2;
                    ull x01 = pk(xr[0].x, xr[1].x), x23 = pk(xr[2].x, xr[3].x);
                    #pragma unroll
                    for (int j = 0; j < 8; j++) {
                        fma2(a[0][j], x01, hl[j - kk + 7]);
                        fma2(a[1][j], x23, hl[j - kk + 7]);
                    }
                }
                // kk = 2*kk2+1 (hi halves)
                {
                    int kk = kk2 * 2 + 1;
                    ull x01 = pk(xr[0].y, xr[1].y), x23 = pk(xr[2].y, xr[3].y);
                    #pragma unroll
                    for (int j = 0; j < 8; j++) {
                        fma2(a[0][j], x01, hl[j - kk + 7]);
                        fma2(a[1][j], x23, hl[j - kk + 7]);
                    }
                }
            }
            if (k8 < 56) {
                #pragma unroll
                for (int m = 14; m >= 8; m--) hl[m] = hl[m - 8];
                int nb = c0 - k8 - 8 + 57;
                #pragma unroll
                for (int m = 0; m < 8; m++) hl[m] = pk2(hb[nb + m]);
            }
        }

        // epilogue: m0_new, mx_new (compute+stash A_bar)
        #pragma unroll
        for (int i = 0; i < 4; i++) {
            int row = r0 + i;
            int off = row * 64 + c0;
            float4 dv0 = *(const float4*)(g_delta + off_bd + off);
            float4 dv1 = *(const float4*)(g_delta + off_bd + off + 4);
            float4 uv0 = *(const float4*)(u + off_bd + off);
            float4 uv1 = *(const float4*)(u + off_bd + off + 4);
            float4 bv0 = *(const float4*)(g_Bval + off_bn + off);
            float4 bv1 = *(const float4*)(g_Bval + off_bn + off + 4);
            float4 mx0 = *(const float4*)(sprev + p1 + off);
            float4 mx1 = *(const float4*)(sprev + p1 + off + 4);
            float dd[8] = { dv0.x, dv0.y, dv0.z, dv0.w, dv1.x, dv1.y, dv1.z, dv1.w };
            float uu[8] = { uv0.x, uv0.y, uv0.z, uv0.w, uv1.x, uv1.y, uv1.z, uv1.w };
            float bb[8] = { bv0.x, bv0.y, bv0.z, bv0.w, bv1.x, bv1.y, bv1.z, bv1.w };
            float mx[8] = { mx0.x, mx0.y, mx0.z, mx0.w, mx1.x, mx1.y, mx1.z, mx1.w };
            float m0n[8], mxn[8];
            #pragma unroll
            for (int j = 0; j < 8; j++) {
                float2 tt = up2(a[i >> 1][j]);
                float gx = (i & 1) ? tt.y : tt.x;
                float m0v = Xs[row * 68 + c0 + j + gap2];
                float Ab = __expf(dd[j] * Ad);
                Abs[i * 8 + j] = Ab;
                m0n[j] = fmaf(Ab, m0v, dd[j] * bb[j] * uu[j]);
                mxn[j] = Ab * (mx[j] - gx);
            }
            *(float4*)(out + so + p0 + off)     = make_float4(m0n[0], m0n[1], m0n[2], m0n[3]);
            *(float4*)(out + so + p0 + off + 4) = make_float4(m0n[4], m0n[5], m0n[6], m0n[7]);
            *(float4*)(out + so + p1 + off)     = make_float4(mxn[0], mxn[1], mxn[2], mxn[3]);
            *(float4*)(out + so + p1 + off + 4) = make_float4(mxn[4], mxn[5], mxn[6], mxn[7]);
        }
    }

    // ===== Phase 2: Gy[r][c] = sum_k h[r-k] X[k][c], pack over col pairs ====
    {
        ull g2[4][4];
        #pragma unroll
        for (int i = 0; i < 4; i++)
            #pragma unroll
            for (int q = 0; q < 4; q++) g2[i][q] = 0ull;

        #pragma unroll 1
        for (int k8 = 0; k8 < 64; k8 += 8) {
            ull gl[11];
            int base = r0 - k8 + 57;
            #pragma unroll
            for (int m = 0; m < 11; m++) gl[m] = pk2(hb[base + m]);
            #pragma unroll
            for (int kk = 0; kk < 8; kk++) {
                int ro = (k8 + kk) * 68 + c0 + gap2;   // even -> 8B aligned
                const ull* xrow = (const ull*)&Xs[ro];
                ull xq[4];
                #pragma unroll
                for (int q = 0; q < 4; q++) xq[q] = xrow[q];
                #pragma unroll
                for (int i = 0; i < 4; i++)
                    #pragma unroll
                    for (int q = 0; q < 4; q++)
                        fma2(g2[i][q], gl[i - kk + 7], xq[q]);
            }
        }

        // epilogue: my_new (A_bar from registers)
        #pragma unroll
        for (int i = 0; i < 4; i++) {
            int row = r0 + i;
            int off = row * 64 + c0;
            float4 my0 = *(const float4*)(sprev + p2 + off);
            float4 my1 = *(const float4*)(sprev + p2 + off + 4);
            float my[8] = { my0.x, my0.y, my0.z, my0.w, my1.x, my1.y, my1.z, my1.w };
            float myn[8];
            #pragma unroll
            for (int j = 0; j < 8; j++) {
                float2 tt = up2(g2[i][j >> 1]);
                float gy = (j & 1) ? tt.y : tt.x;
                myn[j] = Abs[i * 8 + j] * (my[j] - gy);
            }
            *(float4*)(out + so + p2 + off)     = make_float4(myn[0], myn[1], myn[2], myn[3]);
            *(float4*)(out + so + p2 + off + 4) = make_float4(myn[4], myn[5], myn[6], myn[7]);
        }
    }
}

// ---------------------------------------------------------------------------
// K4: y[b,d,p] = sum_n m0_new[b,d,n,p] * C_val[b,n,p] + u*D[d]  (float4)
// ---------------------------------------------------------------------------
__global__ void k_y(const float* __restrict__ u, const float* __restrict__ Dp,
                    float* __restrict__ out) {
    int idx4 = blockIdx.x * 256 + threadIdx.x;   // < 262144
    int b = idx4 >> 16;
    int d = (idx4 >> 10) & 63;
    int p4 = idx4 & 1023;
    const int so = NB * DM * HW;
    const float4* m0n = (const float4*)(out + so + ((b * 3 * 64 + d) * 16) * HW) + p4;
    const float4* Cv  = (const float4*)(g_Cval + (b * 16) * HW) + p4;
    float4 a = make_float4(0.f, 0.f, 0.f, 0.f);
    #pragma unroll
    for (int nn = 0; nn < 16; nn++) {
        float4 m = m0n[nn * 1024];
        float4 c = Cv[nn * 1024];
        a.x = fmaf(m.x, c.x, a.x); a.y = fmaf(m.y, c.y, a.y);
        a.z = fmaf(m.z, c.z, a.z); a.w = fmaf(m.w, c.w, a.w);
    }
    float Dd = Dp[d];
    float4 uv = ((const float4*)u)[idx4];
    a.x = fmaf(uv.x, Dd, a.x); a.y = fmaf(uv.y, Dd, a.y);
    a.z = fmaf(uv.z, Dd, a.z); a.w = fmaf(uv.w, Dd, a.w);
    ((float4*)out)[idx4] = a;
}

// ---------------------------------------------------------------------------
extern "C" void kernel_launch(void* const* d_in, const int* in_sizes, int n_in,
                              void* d_out, int out_size) {
    const float* u     = (const float*)d_in[0];
    const float* sprev = (const float*)d_in[1];
    const float* gamma = (const float*)d_in[2];
    const float* beta  = (const float*)d_in[3];
    const float* wd    = (const float*)d_in[4];
    const float* bd    = (const float*)d_in[5];
    const float* wB    = (const float*)d_in[6];
    const float* wC    = (const float*)d_in[7];
    const float* logA  = (const float*)d_in[8];
    const float* Dp    = (const float*)d_in[9];
    const float* dt    = (const float*)d_in[10];
    float* out = (float*)d_out;

    k_init_h<<<1, 64>>>();
    k_stats<<<256, 256>>>(u);
    k_conv<<<512, 128>>>(u, gamma, beta, wd, bd, wB, wC, dt);
    k_update<<<4096, 128>>>(u, sprev, logA, out);
    k_y<<<1024, 256>>>(u, Dp, out);
}